// round 1
// baseline (speedup 1.0000x reference)
#include <cuda_runtime.h>
#include <cuda_bf16.h>

// Problem constants (fixed by setup_inputs):
//   x: (B=8, C*K=4096, L=2048) fp32  ->  out: (B=8, C=256, L*S=16384) fp32
//   K=16, STRIDE=8, DILATION=1
// Adjoint relation: out[b, c, 8t + (k-15)] += x[b, c*16+k, t]
// Each output p gets at most 2 contributions; inverted to a gather:
//   for p = 8j + r:
//     r=0:    x[k=15, t=j]   + x[k=7,  t=j+1]
//     r=1..7: x[k=7+r,t=j+1] + x[k=r-1,t=j+2]
// (terms dropped when t out of [0, L))

namespace {
constexpr int B = 8;
constexpr int C = 256;
constexpr int K = 16;
constexpr int L = 2048;
constexpr int S = 8;
constexpr int LOUT = L * S;       // 16384
constexpr int J = LOUT / S;       // 2048 output groups per (b,c)
constexpr int TOTAL_THREADS = B * C * J;  // 4,194,304
}

__global__ void __launch_bounds__(256)
fold_transpose_kernel(const float* __restrict__ x, float* __restrict__ out) {
    int idx = blockIdx.x * blockDim.x + threadIdx.x;
    // idx -> (bc, j); lanes take consecutive j for coalesced row reads
    int j  = idx & (J - 1);
    int bc = idx >> 11;           // b*C + c

    const float* xp = x + (size_t)bc * (K * L);

    float acc[8];
#pragma unroll
    for (int r = 0; r < 8; ++r) acc[r] = 0.0f;

    // t = j, k = 15 -> contributes to r = 0
    acc[0] = __ldg(xp + 15 * L + j);

    // t = j+1, k = 7+r -> contributes to r = 0..7
    if (j + 1 < L) {
        const float* row = xp + (j + 1);
#pragma unroll
        for (int r = 0; r < 8; ++r) acc[r] += __ldg(row + (7 + r) * L);
    }

    // t = j+2, k = r-1 -> contributes to r = 1..7
    if (j + 2 < L) {
        const float* row = xp + (j + 2);
#pragma unroll
        for (int r = 1; r < 8; ++r) acc[r] += __ldg(row + (r - 1) * L);
    }

    // 8 consecutive outputs -> two aligned float4 stores
    float4* o = reinterpret_cast<float4*>(out + (size_t)bc * LOUT + 8 * (size_t)j);
    o[0] = make_float4(acc[0], acc[1], acc[2], acc[3]);
    o[1] = make_float4(acc[4], acc[5], acc[6], acc[7]);
}

extern "C" void kernel_launch(void* const* d_in, const int* in_sizes, int n_in,
                              void* d_out, int out_size) {
    (void)in_sizes; (void)n_in; (void)out_size;
    const float* x = (const float*)d_in[0];
    float* out = (float*)d_out;

    constexpr int BLOCK = 256;
    constexpr int GRID = TOTAL_THREADS / BLOCK;  // 16384
    fold_transpose_kernel<<<GRID, BLOCK>>>(x, out);
}

// round 2
// speedup vs baseline: 1.0005x; 1.0005x over previous
#include <cuda_runtime.h>
#include <cuda_bf16.h>

// x: (B=8, C*K=4096, L=2048) fp32 -> out: (B=8, C=256, L*S=16384) fp32
// K=16, STRIDE=8, DILATION=1
// Adjoint: out[b, c, 8t + (k-15)] += x[b, c*16+k, t]  (positions < 0 dropped)
// Inverted to a gather; for output group p = 8j + r:
//   r=0:    x[k=15, t=j]   + x[k=7,  t=j+1]
//   r=1..7: x[k=7+r,t=j+1] + x[k=r-1,t=j+2]
// Terms with t >= L are dropped (handled by zero-filled smem edge columns).

namespace {
constexpr int B = 8;
constexpr int C = 256;
constexpr int K = 16;
constexpr int L = 2048;
constexpr int S = 8;
constexpr int LOUT = L * S;        // 16384
constexpr int J = L;               // output groups per (b,c) = 2048
constexpr int TJ = 256;            // j-tile per block
constexpr int TILES_PER_BC = J / TJ;   // 8
constexpr int ROWSTRIDE = 260;     // 258 used cols, padded to /4 for STS.128 alignment
}

__global__ void __launch_bounds__(256)
fold_transpose_smem_kernel(const float* __restrict__ x, float* __restrict__ out) {
    __shared__ float sm[K][ROWSTRIDE];

    const int tid = threadIdx.x;
    const int bc = blockIdx.x >> 3;                 // / TILES_PER_BC
    const int jstart = (blockIdx.x & 7) << 8;       // * TJ

    const float* xp = x + (size_t)bc * (K * L) + jstart;   // row 0, col jstart (16B aligned)

    // ---- Stage tile: 16 rows x 256 cols via aligned LDG.128 (4 per thread) ----
#pragma unroll
    for (int it = 0; it < 4; ++it) {
        int i = tid + it * 256;        // 0..1023
        int row = i >> 6;              // / 64
        int c4 = i & 63;
        float4 v = __ldg(reinterpret_cast<const float4*>(xp + row * L) + c4);
        *reinterpret_cast<float4*>(&sm[row][c4 * 4]) = v;
    }
    // ---- Edge cols 256, 257 (zero when out of range -> branch-free compute) ----
    if (tid < 32) {
        int row = tid >> 1;
        int c = 256 + (tid & 1);
        int gcol = jstart + c;
        sm[row][c] = (gcol < L) ? __ldg(xp + row * L + c) : 0.0f;
    }
    __syncthreads();

    // ---- Compute: one output group of 8 per thread, pure LDS + FADD ----
    const int t0 = tid;        // col for t=j
    const int t1 = tid + 1;    // col for t=j+1
    const int t2 = tid + 2;    // col for t=j+2

    float acc[8];
    acc[0] = sm[15][t0] + sm[7][t1];
#pragma unroll
    for (int r = 1; r < 8; ++r)
        acc[r] = sm[7 + r][t1] + sm[r - 1][t2];

    // ---- 8 consecutive outputs -> two aligned float4 stores ----
    float4* o = reinterpret_cast<float4*>(
        out + (size_t)bc * LOUT + 8 * (size_t)(jstart + tid));
    o[0] = make_float4(acc[0], acc[1], acc[2], acc[3]);
    o[1] = make_float4(acc[4], acc[5], acc[6], acc[7]);
}

extern "C" void kernel_launch(void* const* d_in, const int* in_sizes, int n_in,
                              void* d_out, int out_size) {
    (void)in_sizes; (void)n_in; (void)out_size;
    const float* x = (const float*)d_in[0];
    float* out = (float*)d_out;

    constexpr int GRID = B * C * TILES_PER_BC;  // 16384
    fold_transpose_smem_kernel<<<GRID, 256>>>(x, out);
}